// round 16
// baseline (speedup 1.0000x reference)
#include <cuda_runtime.h>

#define BATCH 8
#define NCH   6
#define HH    1024
#define WW    1024
#define TY    18          // nominal output rows per block
#define NYT   57          // y-tiles per image (56*18 + 16)
#define NBLOCKS (NYT * BATCH)
#define NPIX  (8.0f * 1024.0f * 1024.0f)
#define PIX_PER_B (HH * WW)
#define CH_STRIDE4 (PIX_PER_B / 4)
#define RAWW  (WW + 8)    // 4 pad cols each side

__device__ float g_partial;
__device__ int   g_done;

__device__ __forceinline__ unsigned fld_lo(unsigned w) { return w & 0x00FF00FFu; }
__device__ __forceinline__ unsigned fld_hi(unsigned w) { return (w >> 8) & 0x00FF00FFu; }

// Single-pass kernel, software-pipelined: classify loads for step s+1 are
// issued between the two barriers of step s, so every warp keeps ~8 LDG.128
// outstanding through the horiz/vertical compute and both barrier waits.
// Layout identical to R15: 456 blocks x 512 threads (~3/SM), full-width row
// bands, 2 rows/step, packed integer moments (exact).
__global__ __launch_bounds__(512, 3) void dcl_onepass(
    const float* __restrict__ pred, const void* __restrict__ tgt,
    float* __restrict__ out)
{
    __shared__ unsigned hbuf[8][WW];     // 32 KB circular horizontal-sum rows
    __shared__ unsigned raw[2][RAWW];    // 8.1 KB moment rows (+4 pad/side)
    __shared__ float    warpsum[16];

    const int tid      = threadIdx.x;
    const int by       = blockIdx.x * TY;
    const int batch    = blockIdx.y;
    const int rows_out = min(TY, HH - by);
    const int S_last   = rows_out / 2 + 1;       // steps s = 0..S_last

    // Targets in [0,5]; little-endian int64 => odd 32-bit words of the first
    // 64 elements all zero. P(false positive for int32) = (1/6)^32 ~ 0.
    const int lane  = tid & 31;
    const int probe = ((const int*)tgt)[2 * lane + 1];
    const int is64  = (__ballot_sync(0xffffffffu, probe != 0) == 0u);

    const float*     pbase = pred + (size_t)batch * NCH * PIX_PER_B;
    const long long* tb64  = (const long long*)tgt + (size_t)batch * PIX_PER_B;
    const int*       tb32  = (const int*)tgt       + (size_t)batch * PIX_PER_B;

    // Zero the pad columns of raw (written once, never overwritten).
    if (tid < 16) {
        const int rr = tid >> 3, j = tid & 7;
        raw[rr][j < 4 ? j : WW + j] = 0u;   // idx 0..3 and 1028..1031
    }

    const int srow = tid >> 8;          // 0..1: row within step
    const int cg   = (tid & 255) * 4;   // column base of this thread's group
    const int c0   = tid * 2;           // vertical: 2 fixed columns

    unsigned sa0 = 0, sb0 = 0, sa1 = 0, sb1 = 0;   // vertical window state
    int   acc_i = 0;
    float acc_s = 0.0f;

    // Classify one 2-row pair (argmax over channels + moment pack).
    auto classify = [&](int gy) -> uint4 {
        uint4 mom = make_uint4(0, 0, 0, 0);
        if ((unsigned)gy < (unsigned)HH) {
            const float4* pp = (const float4*)(pbase + (size_t)gy * WW) + (cg >> 2);
            float4 v[NCH];
            #pragma unroll
            for (int ch = 0; ch < NCH; ++ch) v[ch] = pp[(size_t)ch * CH_STRIDE4];

            int t0, t1, t2, t3;
            if (is64) {
                const int4* tp = (const int4*)(tb64 + (size_t)gy * WW + cg);
                const int4 q0 = tp[0], q1 = tp[1];
                t0 = q0.x; t1 = q0.z; t2 = q1.x; t3 = q1.z;
            } else {
                const int4 q = *(const int4*)(tb32 + (size_t)gy * WW + cg);
                t0 = q.x; t1 = q.y; t2 = q.z; t3 = q.w;
            }

            int i0 = 0, i1 = 0, i2 = 0, i3 = 0;
            float m0 = v[0].x, m1 = v[0].y, m2 = v[0].z, m3 = v[0].w;
            #pragma unroll
            for (int ch = 1; ch < NCH; ++ch) {
                if (v[ch].x > m0) { m0 = v[ch].x; i0 = ch; }
                if (v[ch].y > m1) { m1 = v[ch].y; i1 = ch; }
                if (v[ch].z > m2) { m2 = v[ch].z; i2 = ch; }
                if (v[ch].w > m3) { m3 = v[ch].w; i3 = ch; }
            }
            mom.x = (unsigned)i0 * (((unsigned)i0 << 8) + 1u) + (((unsigned)t0 * (((unsigned)t0 << 8) + 1u)) << 16);
            mom.y = (unsigned)i1 * (((unsigned)i1 << 8) + 1u) + (((unsigned)t1 * (((unsigned)t1 << 8) + 1u)) << 16);
            mom.z = (unsigned)i2 * (((unsigned)i2 << 8) + 1u) + (((unsigned)t2 * (((unsigned)t2 << 8) + 1u)) << 16);
            mom.w = (unsigned)i3 * (((unsigned)i3 << 8) + 1u) + (((unsigned)t3 * (((unsigned)t3 << 8) + 1u)) << 16);
        }
        return mom;
    };

    // Prologue: classify step 0.
    uint4 mom = classify(by - 2 + srow);

    for (int s = 0; s <= S_last; ++s) {
        // ---- publish this step's moments ----
        *(uint4*)&raw[srow][4 + cg] = mom;
        __syncthreads();   // bar A: raw visible; prior-step horiz reads done

        // ---- horizontal 5-sums for the 2 new rows ----
        const uint4 A = *(const uint4*)&raw[srow][cg];       // cols cg-4..cg-1
        const uint4 B = *(const uint4*)&raw[srow][cg + 4];   // cols cg..cg+3
        const uint4 C = *(const uint4*)&raw[srow][cg + 8];   // cols cg+4..cg+7

        // ---- software pipeline: issue next step's loads NOW ----
        if (s < S_last) mom = classify(by - 2 + 2 * (s + 1) + srow);

        {
            unsigned ss = A.z + A.w + B.x + B.y + B.z;
            uint4 o;
            o.x = ss; ss += B.w - A.z;
            o.y = ss; ss += C.x - A.w;
            o.z = ss; ss += C.y - B.x;
            o.w = ss;
            *(uint4*)&hbuf[(2 * s + srow) & 7][cg] = o;
        }
        __syncthreads();   // bar B: hbuf rows 2s,2s+1 ready; raw reads done

        // ---- vertical sliding window: 2 output rows, 2 cols/thread ----
        if (s >= 2) {
            if (s == 2) {
                #pragma unroll
                for (int d = 0; d < 5; ++d) {
                    const uint2 w = *(const uint2*)&hbuf[d][c0];
                    sa0 += fld_lo(w.x); sb0 += fld_hi(w.x);
                    sa1 += fld_lo(w.y); sb1 += fld_hi(w.y);
                }
            } else {
                const uint2 nw = *(const uint2*)&hbuf[(2 * s) & 7][c0];
                const uint2 ow = *(const uint2*)&hbuf[(2 * s - 5) & 7][c0];
                sa0 += fld_lo(nw.x) - fld_lo(ow.x); sb0 += fld_hi(nw.x) - fld_hi(ow.x);
                sa1 += fld_lo(nw.y) - fld_lo(ow.y); sb1 += fld_hi(nw.y) - fld_hi(ow.y);
            }
            #pragma unroll
            for (int half = 0; half < 2; ++half) {
                {
                    const unsigned q = sb0 * 25u;
                    const int s1c = (int)(sa0 & 0xFFFFu), s1t = (int)(sa0 >> 16);
                    const int np = (int)(q & 0xFFFFu) - s1c * s1c;
                    const int nt = (int)(q >> 16)     - s1t * s1t;
                    acc_i += np + nt;
                    const float p = (float)(np * nt);
                    float sq;
                    asm("sqrt.approx.f32 %0, %1;" : "=f"(sq) : "f"(p));
                    acc_s += sq;
                }
                {
                    const unsigned q = sb1 * 25u;
                    const int s1c = (int)(sa1 & 0xFFFFu), s1t = (int)(sa1 >> 16);
                    const int np = (int)(q & 0xFFFFu) - s1c * s1c;
                    const int nt = (int)(q >> 16)     - s1t * s1t;
                    acc_i += np + nt;
                    const float p = (float)(np * nt);
                    float sq;
                    asm("sqrt.approx.f32 %0, %1;" : "=f"(sq) : "f"(p));
                    acc_s += sq;
                }
                if (half == 0) {   // slide to second output row of this step
                    const uint2 nw = *(const uint2*)&hbuf[(2 * s + 1) & 7][c0];
                    const uint2 ow = *(const uint2*)&hbuf[(2 * s - 4) & 7][c0];
                    sa0 += fld_lo(nw.x) - fld_lo(ow.x); sb0 += fld_hi(nw.x) - fld_hi(ow.x);
                    sa1 += fld_lo(nw.y) - fld_lo(ow.y); sb1 += fld_hi(nw.y) - fld_hi(ow.y);
                }
            }
        }
    }

    // ---- Reduce: warp shuffle -> smem -> one atomic per block ----
    float acc = fmaf(-2.0f, acc_s, (float)acc_i) * (1.0f / (600.0f * NPIX));
    #pragma unroll
    for (int o = 16; o > 0; o >>= 1)
        acc += __shfl_down_sync(0xffffffffu, acc, o);

    if ((tid & 31) == 0) warpsum[tid >> 5] = acc;
    __syncthreads();
    if (tid < 16) {
        float v = warpsum[tid];
        #pragma unroll
        for (int o = 8; o > 0; o >>= 1)
            v += __shfl_down_sync(0xffffu, v, o);
        if (tid == 0) {
            atomicAdd(&g_partial, v);
            __threadfence();
            const int old = atomicAdd(&g_done, 1);
            if (old == NBLOCKS - 1) {
                // Last block: publish and reset for the next graph replay.
                *out = atomicAdd(&g_partial, 0.0f);
                g_partial = 0.0f;
                g_done = 0;
                __threadfence();
            }
        }
    }
}

extern "C" void kernel_launch(void* const* d_in, const int* in_sizes, int n_in,
                              void* d_out, int out_size) {
    const float* pred = (const float*)d_in[0];
    const void*  tgt  = d_in[1];
    float* out = (float*)d_out;

    dim3 grid(NYT, BATCH);
    dcl_onepass<<<grid, 512>>>(pred, tgt, out);
}

// round 17
// speedup vs baseline: 1.0196x; 1.0196x over previous
#include <cuda_runtime.h>

#define BATCH 8
#define NCH   6
#define HH    1024
#define WW    1024
#define NBLOCKS 444       // = 148 SMs x 3 resident blocks: one perfectly balanced wave
#define NPIX  (8.0f * 1024.0f * 1024.0f)
#define PIX_PER_B (HH * WW)
#define CH_STRIDE4 (PIX_PER_B / 4)
#define RAWW  (WW + 8)    // 4 pad cols each side

__device__ float g_partial;
__device__ int   g_done;

__device__ __forceinline__ unsigned fld_lo(unsigned w) { return w & 0x00FF00FFu; }
__device__ __forceinline__ unsigned fld_hi(unsigned w) { return (w >> 8) & 0x00FF00FFu; }

// Single-pass kernel: 444 blocks x 512 threads = exactly 3 blocks on every SM
// (no partial 4th-block tail). Band heights are mixed (18 or 20 rows, even) so
// the 8 x 1024-row images split exactly across 444 blocks:
//   images 0-3: 56 blocks = 48x18 + 8x20 rows
//   images 4-7: 55 blocks = 38x18 + 17x20 rows
// Per block: full-width row band, row-streaming pipeline (2 rows/step):
// classify -> raw moments (smem) -> horizontal 5-sums (8-row circular smem) ->
// vertical sliding window (regs). Moment word: cv | cv^2<<8 | tv<<16 | tv^2<<24
// (cv,tv in [0,5]); horizontal 5-sums 25/125/25/125 (no carry); vertical sums
// split into 16-bit-field accumulators (<=125 / <=625). All integer-exact.
__global__ __launch_bounds__(512, 3) void dcl_onepass(
    const float* __restrict__ pred, const void* __restrict__ tgt,
    float* __restrict__ out)
{
    __shared__ unsigned hbuf[8][WW];     // 32 KB circular horizontal-sum rows
    __shared__ unsigned raw[2][RAWW];    // 8.1 KB moment rows (+4 pad/side)
    __shared__ float    warpsum[16];

    const int tid = threadIdx.x;
    const int bid = blockIdx.x;

    // ---- band assignment: balanced 444-block split ----
    int batch, idx;
    if (bid < 224) { batch = bid / 56;        idx = bid % 56; }
    else           { batch = 4 + (bid - 224) / 55; idx = (bid - 224) % 55; }
    const int n18 = (batch < 4) ? 48 : 38;   // bands of 18 before the 20s
    int by, rows_out;
    if (idx < n18) { by = 18 * idx;                      rows_out = 18; }
    else           { by = 18 * n18 + 20 * (idx - n18);   rows_out = 20; }
    const int S_last = rows_out / 2 + 1;     // steps s = 0..S_last

    // Targets in [0,5]; little-endian int64 => odd 32-bit words of the first
    // 64 elements all zero. P(false positive for int32) = (1/6)^32 ~ 0.
    const int lane  = tid & 31;
    const int probe = ((const int*)tgt)[2 * lane + 1];
    const int is64  = (__ballot_sync(0xffffffffu, probe != 0) == 0u);

    const float*     pbase = pred + (size_t)batch * NCH * PIX_PER_B;
    const long long* tb64  = (const long long*)tgt + (size_t)batch * PIX_PER_B;
    const int*       tb32  = (const int*)tgt       + (size_t)batch * PIX_PER_B;

    // Zero the pad columns of raw (written once, never overwritten).
    if (tid < 16) {
        const int rr = tid >> 3, j = tid & 7;
        raw[rr][j < 4 ? j : WW + j] = 0u;   // idx 0..3 and 1028..1031
    }

    const int srow = tid >> 8;          // 0..1: row within step
    const int cg   = (tid & 255) * 4;   // column base of this thread's group
    const int c0   = tid * 2;           // vertical: 2 fixed columns

    unsigned sa0 = 0, sb0 = 0, sa1 = 0, sb1 = 0;   // vertical window state
    int   acc_i = 0;
    float acc_s = 0.0f;

    for (int s = 0; s <= S_last; ++s) {
        // ---- classify 2 rows: argmax + moment pack ----
        const int gy = by - 2 + 2 * s + srow;
        uint4 mom = make_uint4(0, 0, 0, 0);
        if ((unsigned)gy < (unsigned)HH) {
            const float4* pp = (const float4*)(pbase + (size_t)gy * WW) + (cg >> 2);
            float4 v[NCH];
            #pragma unroll
            for (int ch = 0; ch < NCH; ++ch) v[ch] = pp[(size_t)ch * CH_STRIDE4];

            int t0, t1, t2, t3;
            if (is64) {
                const int4* tp = (const int4*)(tb64 + (size_t)gy * WW + cg);
                const int4 q0 = tp[0], q1 = tp[1];
                t0 = q0.x; t1 = q0.z; t2 = q1.x; t3 = q1.z;
            } else {
                const int4 q = *(const int4*)(tb32 + (size_t)gy * WW + cg);
                t0 = q.x; t1 = q.y; t2 = q.z; t3 = q.w;
            }

            int i0 = 0, i1 = 0, i2 = 0, i3 = 0;
            float m0 = v[0].x, m1 = v[0].y, m2 = v[0].z, m3 = v[0].w;
            #pragma unroll
            for (int ch = 1; ch < NCH; ++ch) {
                if (v[ch].x > m0) { m0 = v[ch].x; i0 = ch; }
                if (v[ch].y > m1) { m1 = v[ch].y; i1 = ch; }
                if (v[ch].z > m2) { m2 = v[ch].z; i2 = ch; }
                if (v[ch].w > m3) { m3 = v[ch].w; i3 = ch; }
            }
            mom.x = (unsigned)i0 * (((unsigned)i0 << 8) + 1u) + (((unsigned)t0 * (((unsigned)t0 << 8) + 1u)) << 16);
            mom.y = (unsigned)i1 * (((unsigned)i1 << 8) + 1u) + (((unsigned)t1 * (((unsigned)t1 << 8) + 1u)) << 16);
            mom.z = (unsigned)i2 * (((unsigned)i2 << 8) + 1u) + (((unsigned)t2 * (((unsigned)t2 << 8) + 1u)) << 16);
            mom.w = (unsigned)i3 * (((unsigned)i3 << 8) + 1u) + (((unsigned)t3 * (((unsigned)t3 << 8) + 1u)) << 16);
        }
        *(uint4*)&raw[srow][4 + cg] = mom;
        __syncthreads();

        // ---- horizontal 5-sums for the 2 new rows ----
        {
            const uint4 A = *(const uint4*)&raw[srow][cg];       // cols cg-4..cg-1
            const uint4 B = *(const uint4*)&raw[srow][cg + 4];   // cols cg..cg+3
            const uint4 C = *(const uint4*)&raw[srow][cg + 8];   // cols cg+4..cg+7
            unsigned ss = A.z + A.w + B.x + B.y + B.z;
            uint4 o;
            o.x = ss; ss += B.w - A.z;
            o.y = ss; ss += C.x - A.w;
            o.z = ss; ss += C.y - B.x;
            o.w = ss;
            *(uint4*)&hbuf[(2 * s + srow) & 7][cg] = o;
        }
        __syncthreads();

        // ---- vertical sliding window: 2 output rows, 2 cols/thread ----
        if (s >= 2) {
            if (s == 2) {
                #pragma unroll
                for (int d = 0; d < 5; ++d) {
                    const uint2 w = *(const uint2*)&hbuf[d][c0];
                    sa0 += fld_lo(w.x); sb0 += fld_hi(w.x);
                    sa1 += fld_lo(w.y); sb1 += fld_hi(w.y);
                }
            } else {
                const uint2 nw = *(const uint2*)&hbuf[(2 * s) & 7][c0];
                const uint2 ow = *(const uint2*)&hbuf[(2 * s - 5) & 7][c0];
                sa0 += fld_lo(nw.x) - fld_lo(ow.x); sb0 += fld_hi(nw.x) - fld_hi(ow.x);
                sa1 += fld_lo(nw.y) - fld_lo(ow.y); sb1 += fld_hi(nw.y) - fld_hi(ow.y);
            }
            #pragma unroll
            for (int half = 0; half < 2; ++half) {
                {
                    const unsigned q = sb0 * 25u;
                    const int s1c = (int)(sa0 & 0xFFFFu), s1t = (int)(sa0 >> 16);
                    const int np = (int)(q & 0xFFFFu) - s1c * s1c;
                    const int nt = (int)(q >> 16)     - s1t * s1t;
                    acc_i += np + nt;
                    const float p = (float)(np * nt);
                    float sq;
                    asm("sqrt.approx.f32 %0, %1;" : "=f"(sq) : "f"(p));
                    acc_s += sq;
                }
                {
                    const unsigned q = sb1 * 25u;
                    const int s1c = (int)(sa1 & 0xFFFFu), s1t = (int)(sa1 >> 16);
                    const int np = (int)(q & 0xFFFFu) - s1c * s1c;
                    const int nt = (int)(q >> 16)     - s1t * s1t;
                    acc_i += np + nt;
                    const float p = (float)(np * nt);
                    float sq;
                    asm("sqrt.approx.f32 %0, %1;" : "=f"(sq) : "f"(p));
                    acc_s += sq;
                }
                if (half == 0) {   // slide to second output row of this step
                    const uint2 nw = *(const uint2*)&hbuf[(2 * s + 1) & 7][c0];
                    const uint2 ow = *(const uint2*)&hbuf[(2 * s - 4) & 7][c0];
                    sa0 += fld_lo(nw.x) - fld_lo(ow.x); sb0 += fld_hi(nw.x) - fld_hi(ow.x);
                    sa1 += fld_lo(nw.y) - fld_lo(ow.y); sb1 += fld_hi(nw.y) - fld_hi(ow.y);
                }
            }
        }
    }

    // ---- Reduce: warp shuffle -> smem -> one atomic per block ----
    float acc = fmaf(-2.0f, acc_s, (float)acc_i) * (1.0f / (600.0f * NPIX));
    #pragma unroll
    for (int o = 16; o > 0; o >>= 1)
        acc += __shfl_down_sync(0xffffffffu, acc, o);

    if ((tid & 31) == 0) warpsum[tid >> 5] = acc;
    __syncthreads();
    if (tid < 16) {
        float v = warpsum[tid];
        #pragma unroll
        for (int o = 8; o > 0; o >>= 1)
            v += __shfl_down_sync(0xffffu, v, o);
        if (tid == 0) {
            atomicAdd(&g_partial, v);
            __threadfence();
            const int old = atomicAdd(&g_done, 1);
            if (old == NBLOCKS - 1) {
                // Last block: publish and reset for the next graph replay.
                *out = atomicAdd(&g_partial, 0.0f);
                g_partial = 0.0f;
                g_done = 0;
                __threadfence();
            }
        }
    }
}

extern "C" void kernel_launch(void* const* d_in, const int* in_sizes, int n_in,
                              void* d_out, int out_size) {
    const float* pred = (const float*)d_in[0];
    const void*  tgt  = d_in[1];
    float* out = (float*)d_out;

    dcl_onepass<<<NBLOCKS, 512>>>(pred, tgt, out);
}